// round 1
// baseline (speedup 1.0000x reference)
#include <cuda_runtime.h>
#include <cuda_bf16.h>
#include <math.h>

#define TT   512
#define BB   64
#define HH   512
#define LL   2
#define NBLK 128          // recurrence grid size (must be <= 148 for co-residency)

// ---------------- scratch (allocation-free: __device__ globals) ----------------
__device__ float g_gx[3][TT * BB * HH];   // gate-x planes for current layer (r,z,n)
__device__ float g_h[2][BB * HH];         // double-buffered hidden state [b][k]
__device__ unsigned long long g_bar;      // grid barrier ticket counter

// ---------------- input-side GEMM: C = A(M,K) * W(K,N) + bias --------------------
// M = T*B = 32768, K = H = 512, N = H = 512 (one gate per launch)
// BM=128, BN=64, BK=16, 256 threads, 8x4 per-thread tile, double-buffered smem.
__global__ __launch_bounds__(256) void gemm_xw(const float* __restrict__ A,
                                               const float* __restrict__ W,
                                               const float* __restrict__ bias,
                                               int gate) {
    __shared__ float As[2][16][128];
    __shared__ float Ws[2][16][64];

    const int bm = blockIdx.x * 128;
    const int bn = blockIdx.y * 64;
    const int tid = threadIdx.x;

    // A loader mapping: 2 float4 per thread
    const int ar = tid >> 2;          // 0..63
    const int ak = (tid & 3) << 2;    // 0,4,8,12
    // W loader mapping: 1 float4 per thread
    const int wk = tid >> 4;          // 0..15
    const int wn = (tid & 15) << 2;   // 0..60

    // compute mapping
    const int tn = (tid & 15) << 2;   // 0..60
    const int tm = (tid >> 4) << 3;   // 0..120

    float acc[8][4];
#pragma unroll
    for (int i = 0; i < 8; i++)
#pragma unroll
        for (int j = 0; j < 4; j++) acc[i][j] = 0.f;

    // preload tile 0 into buffer 0
    {
        float4 v0 = *(const float4*)(A + (size_t)(bm + ar) * HH + 0 + ak);
        float4 v1 = *(const float4*)(A + (size_t)(bm + ar + 64) * HH + 0 + ak);
        As[0][ak + 0][ar] = v0.x; As[0][ak + 1][ar] = v0.y;
        As[0][ak + 2][ar] = v0.z; As[0][ak + 3][ar] = v0.w;
        As[0][ak + 0][ar + 64] = v1.x; As[0][ak + 1][ar + 64] = v1.y;
        As[0][ak + 2][ar + 64] = v1.z; As[0][ak + 3][ar + 64] = v1.w;
        float4 w4 = *(const float4*)(W + (size_t)(0 + wk) * HH + bn + wn);
        *(float4*)&Ws[0][wk][wn] = w4;
    }
    __syncthreads();

    for (int kt = 0; kt < HH; kt += 16) {
        const int buf = (kt >> 4) & 1;
        float4 pa0, pa1, pw;
        const bool more = (kt + 16) < HH;
        if (more) {
            pa0 = *(const float4*)(A + (size_t)(bm + ar) * HH + kt + 16 + ak);
            pa1 = *(const float4*)(A + (size_t)(bm + ar + 64) * HH + kt + 16 + ak);
            pw  = *(const float4*)(W + (size_t)(kt + 16 + wk) * HH + bn + wn);
        }
#pragma unroll
        for (int k = 0; k < 16; k++) {
            float4 a0 = *(const float4*)&As[buf][k][tm];
            float4 a1 = *(const float4*)&As[buf][k][tm + 4];
            float4 bv = *(const float4*)&Ws[buf][k][tn];
            float am[8] = {a0.x, a0.y, a0.z, a0.w, a1.x, a1.y, a1.z, a1.w};
            float bm_[4] = {bv.x, bv.y, bv.z, bv.w};
#pragma unroll
            for (int i = 0; i < 8; i++)
#pragma unroll
                for (int j = 0; j < 4; j++)
                    acc[i][j] = fmaf(am[i], bm_[j], acc[i][j]);
        }
        if (more) {
            const int nb = buf ^ 1;
            As[nb][ak + 0][ar] = pa0.x; As[nb][ak + 1][ar] = pa0.y;
            As[nb][ak + 2][ar] = pa0.z; As[nb][ak + 3][ar] = pa0.w;
            As[nb][ak + 0][ar + 64] = pa1.x; As[nb][ak + 1][ar + 64] = pa1.y;
            As[nb][ak + 2][ar + 64] = pa1.z; As[nb][ak + 3][ar + 64] = pa1.w;
            *(float4*)&Ws[nb][wk][wn] = pw;
        }
        __syncthreads();
    }

    float* C = g_gx[gate];
#pragma unroll
    for (int i = 0; i < 8; i++) {
        const size_t row = (size_t)(bm + tm + i) * HH;
#pragma unroll
        for (int j = 0; j < 4; j++) {
            const int col = bn + tn + j;
            C[row + col] = acc[i][j] + bias[col];
        }
    }
}

// ---------------- grid barrier (all NBLK CTAs co-resident) ----------------------
__device__ __forceinline__ void grid_sync() {
    __syncthreads();
    if (threadIdx.x == 0) {
        __threadfence();
        unsigned long long t = atomicAdd(&g_bar, 1ull) + 1ull;
        unsigned long long target = ((t - 1ull) / NBLK + 1ull) * (unsigned long long)NBLK;
        volatile unsigned long long* vb = &g_bar;
        while (*vb < target) { __nanosleep(64); }
        __threadfence();
    }
    __syncthreads();
}

// ---------------- persistent recurrence: one launch per layer -------------------
// 128 CTAs x 256 threads. CTA owns 4 hidden output columns (all 3 gates).
// Thread (jj = tid&3, b = tid>>2) computes h_new[b][jbase+jj].
#define HPITCH 520                       // padded smem row (bank decorrelation)
#define SMEM_FLOATS (3 * 4 * HPITCH + BB * HPITCH)

__global__ __launch_bounds__(256) void gru_recurrence(
    const float* __restrict__ whr, const float* __restrict__ whz,
    const float* __restrict__ whn,
    const float* __restrict__ bhr, const float* __restrict__ bhz,
    const float* __restrict__ bhn,
    const float* __restrict__ h0,       // [B,H] initial state for this layer
    float* __restrict__ seq,            // [T,B,H] layer output sequence
    float* __restrict__ finals)         // [B,H] final hidden for this layer
{
    extern __shared__ float sm[];
    float* ws = sm;                      // [3*4][HPITCH] weight columns
    float* hs = sm + 3 * 4 * HPITCH;     // [BB][HPITCH] staged h

    const int tid = threadIdx.x;
    const int jbase = blockIdx.x * 4;
    const int jj = tid & 3;
    const int b = tid >> 2;
    const int jglob = jbase + jj;

    // load this CTA's weight columns into smem (once)
    for (int i = tid; i < 3 * 4 * HH; i += 256) {
        const int g = i >> 11;             // /2048
        const int rem = i & 2047;
        const int j = rem >> 9;            // /512
        const int k = rem & 511;
        const float* wsrc = (g == 0) ? whr : ((g == 1) ? whz : whn);
        ws[(g * 4 + j) * HPITCH + k] = wsrc[(size_t)k * HH + jbase + j];
    }
    const float bh_r = bhr[jglob];
    const float bh_z = bhz[jglob];
    const float bh_n = bhn[jglob];
    __syncthreads();

    const float* wr = ws + (0 * 4 + jj) * HPITCH;
    const float* wz = ws + (1 * 4 + jj) * HPITCH;
    const float* wn = ws + (2 * 4 + jj) * HPITCH;
    const float* hrow = hs + b * HPITCH;

    for (int t = 0; t < TT; t++) {
        // stage h_{t-1} into smem (L2-coherent loads)
        const float* hsrc = (t == 0) ? h0 : g_h[(t - 1) & 1];
        const float4* src4 = (const float4*)hsrc;
        for (int i = tid; i < BB * HH / 4; i += 256) {
            const int sb = i >> 7;           // /128
            const int k4 = i & 127;
            float4 v = __ldcg(src4 + sb * 128 + k4);
            *(float4*)&hs[sb * HPITCH + k4 * 4] = v;
        }
        __syncthreads();

        // prefetch gate-x values (hidden under the dot loop)
        const int gi = (t * BB + b) * HH + jglob;
        const float gxr = g_gx[0][gi];
        const float gxz = g_gx[1][gi];
        const float gxn = g_gx[2][gi];

        float ar = bh_r, az = bh_z, an = bh_n;
#pragma unroll 4
        for (int k = 0; k < HH; k += 4) {
            float4 h4 = *(const float4*)(hrow + k);
            float4 r4 = *(const float4*)(wr + k);
            float4 z4 = *(const float4*)(wz + k);
            float4 n4 = *(const float4*)(wn + k);
            ar = fmaf(h4.x, r4.x, ar); ar = fmaf(h4.y, r4.y, ar);
            ar = fmaf(h4.z, r4.z, ar); ar = fmaf(h4.w, r4.w, ar);
            az = fmaf(h4.x, z4.x, az); az = fmaf(h4.y, z4.y, az);
            az = fmaf(h4.z, z4.z, az); az = fmaf(h4.w, z4.w, az);
            an = fmaf(h4.x, n4.x, an); an = fmaf(h4.y, n4.y, an);
            an = fmaf(h4.z, n4.z, an); an = fmaf(h4.w, n4.w, an);
        }

        const float r = 1.f / (1.f + expf(-(gxr + ar)));
        const float z = 1.f / (1.f + expf(-(gxz + az)));
        const float n = tanhf(gxn + r * an);
        const float hp = hrow[jglob];
        const float hn_ = (1.f - z) * n + z * hp;

        __stcg(&g_h[t & 1][b * HH + jglob], hn_);
        seq[gi] = hn_;
        if (t == TT - 1) finals[(size_t)b * HH + jglob] = hn_;

        grid_sync();
    }
}

// -------------------------------- launch ---------------------------------------
extern "C" void kernel_launch(void* const* d_in, const int* in_sizes, int n_in,
                              void* d_out, int out_size) {
    const float* x    = (const float*)d_in[0];
    const float* init = (const float*)d_in[1];
    const float* w_ir = (const float*)d_in[2];
    const float* w_hr = (const float*)d_in[3];
    const float* w_iz = (const float*)d_in[4];
    const float* w_hz = (const float*)d_in[5];
    const float* w_in = (const float*)d_in[6];
    const float* w_hn = (const float*)d_in[7];
    const float* b_ir = (const float*)d_in[8];
    const float* b_hr = (const float*)d_in[9];
    const float* b_iz = (const float*)d_in[10];
    const float* b_hz = (const float*)d_in[11];
    const float* b_in = (const float*)d_in[12];
    const float* b_hn = (const float*)d_in[13];

    float* out    = (float*)d_out;
    float* seq    = out;                      // [T,B,H]
    float* finals = out + (size_t)TT * BB * HH; // [L,B,H]

    const size_t smem_bytes = (size_t)SMEM_FLOATS * sizeof(float);
    cudaFuncSetAttribute(gru_recurrence,
                         cudaFuncAttributeMaxDynamicSharedMemorySize,
                         (int)smem_bytes);

    dim3 ggrid(TT * BB / 128, HH / 64);       // 256 x 8

    for (int l = 0; l < LL; l++) {
        const float* A = (l == 0) ? x : seq;
        const size_t wo = (size_t)l * HH * HH;
        const size_t bo = (size_t)l * HH;

        gemm_xw<<<ggrid, 256>>>(A, w_ir + wo, b_ir + bo, 0);
        gemm_xw<<<ggrid, 256>>>(A, w_iz + wo, b_iz + bo, 1);
        gemm_xw<<<ggrid, 256>>>(A, w_in + wo, b_in + bo, 2);

        gru_recurrence<<<NBLK, 256, smem_bytes>>>(
            w_hr + wo, w_hz + wo, w_hn + wo,
            b_hr + bo, b_hz + bo, b_hn + bo,
            init + (size_t)l * BB * HH,
            seq,
            finals + (size_t)l * BB * HH);
    }
}

// round 2
// speedup vs baseline: 2.0231x; 2.0231x over previous
#include <cuda_runtime.h>
#include <cuda_bf16.h>
#include <math.h>

#define TT   512
#define BB   64
#define HH   512
#define LL   2
#define NBLK 128          // recurrence grid (1 CTA/SM, all co-resident)

typedef unsigned long long ull;

// ---------------- scratch (__device__ globals; allocation-free) ----------------
__device__ float g_gx[3][TT * BB * HH];     // gate-x planes (r,z,n) for current layer
__device__ float g_ht[2][HH * BB];          // double-buffered hidden state, k-major [k][b]
__device__ ull   g_bar;                     // grid barrier ticket

// ---------------- packed fp32x2 helpers (Blackwell) -----------------------------
__device__ __forceinline__ ull pk2(float x) {
    ull r; asm("mov.b64 %0, {%1, %1};" : "=l"(r) : "f"(x)); return r;
}
__device__ __forceinline__ void fma2(ull& acc, ull a, ull b) {
    asm("fma.rn.f32x2 %0, %1, %2, %0;" : "+l"(acc) : "l"(a), "l"(b));
}

// ---------------- input-side GEMM: C = A(M,512) * W(512,512) + bias -------------
// BM=128, BN=128, BK=8, 256 threads, 8x8 per-thread tile, f32x2 accumulation.
__global__ __launch_bounds__(256) void gemm_xw(const float* __restrict__ A,
                                               const float* __restrict__ W,
                                               const float* __restrict__ bias,
                                               int gate) {
    __shared__ float As[2][8][128];
    __shared__ float Ws[2][8][128];

    const int bm = blockIdx.x * 128;
    const int bn = blockIdx.y * 128;
    const int tid = threadIdx.x;

    // loaders: one float4 each
    const int ar = tid >> 1;          // 0..127 (A row)
    const int ak = (tid & 1) << 2;    // 0,4
    const int wk = tid >> 5;          // 0..7
    const int wn = (tid & 31) << 2;   // 0..124

    // compute mapping: 16x16 threads, 8x8 tile
    const int tm = (tid >> 4) << 3;
    const int tn = (tid & 15) << 3;

    ull acc[8][4];
#pragma unroll
    for (int i = 0; i < 8; i++)
#pragma unroll
        for (int j = 0; j < 4; j++) acc[i][j] = 0ull;

    // preload tile 0
    {
        float4 va = *(const float4*)(A + (size_t)(bm + ar) * HH + ak);
        As[0][ak + 0][ar] = va.x; As[0][ak + 1][ar] = va.y;
        As[0][ak + 2][ar] = va.z; As[0][ak + 3][ar] = va.w;
        *(float4*)&Ws[0][wk][wn] = *(const float4*)(W + (size_t)wk * HH + bn + wn);
    }
    __syncthreads();

    for (int kt = 0; kt < HH; kt += 8) {
        const int buf = (kt >> 3) & 1;
        float4 pa, pw;
        const bool more = (kt + 8) < HH;
        if (more) {
            pa = *(const float4*)(A + (size_t)(bm + ar) * HH + kt + 8 + ak);
            pw = *(const float4*)(W + (size_t)(kt + 8 + wk) * HH + bn + wn);
        }
#pragma unroll
        for (int k = 0; k < 8; k++) {
            float4 a0 = *(const float4*)&As[buf][k][tm];
            float4 a1 = *(const float4*)&As[buf][k][tm + 4];
            ulonglong2 b0 = *(const ulonglong2*)&Ws[buf][k][tn];
            ulonglong2 b1 = *(const ulonglong2*)&Ws[buf][k][tn + 4];
            ull bp[4] = {b0.x, b0.y, b1.x, b1.y};
            float am[8] = {a0.x, a0.y, a0.z, a0.w, a1.x, a1.y, a1.z, a1.w};
#pragma unroll
            for (int i = 0; i < 8; i++) {
                ull ap = pk2(am[i]);
#pragma unroll
                for (int j = 0; j < 4; j++) fma2(acc[i][j], ap, bp[j]);
            }
        }
        if (more) {
            const int nb = buf ^ 1;
            As[nb][ak + 0][ar] = pa.x; As[nb][ak + 1][ar] = pa.y;
            As[nb][ak + 2][ar] = pa.z; As[nb][ak + 3][ar] = pa.w;
            *(float4*)&Ws[nb][wk][wn] = pw;
        }
        __syncthreads();
    }

    float* C = g_gx[gate];
#pragma unroll
    for (int i = 0; i < 8; i++) {
        const size_t row = (size_t)(bm + tm + i) * HH;
#pragma unroll
        for (int j = 0; j < 4; j++) {
            const int col = bn + tn + 2 * j;
            float2 v = *(float2*)&acc[i][j];
            v.x += bias[col]; v.y += bias[col + 1];
            *(float2*)&C[row + col] = v;
        }
    }
}

// ---------------- grid barrier ---------------------------------------------------
__device__ __forceinline__ void grid_sync() {
    __syncthreads();
    if (threadIdx.x == 0) {
        __threadfence();
        ull t = atomicAdd(&g_bar, 1ull) + 1ull;
        ull target = ((t - 1ull) / NBLK + 1ull) * (ull)NBLK;
        volatile ull* vb = &g_bar;
        while (*vb < target) { __nanosleep(32); }
        __threadfence();
    }
    __syncthreads();
}

// ---------------- persistent recurrence ------------------------------------------
// 128 CTAs x 256 threads. CTA owns 4 hidden columns (3 gates each).
// Dot phase: warp = k-slice (64 k), lane: btile = lane>>1 (4 batches), ct = lane&1
//   (col pair). acc[g][bb] is f32x2 over the col pair.  Reduce via smem.
// Activation phase: thread (b = tid>>2, j = tid&3).
#define WSM_PITCH 16
#define SMEM_FLOATS (HH * BB + HH * WSM_PITCH + 16 * 192 * 2)

__global__ __launch_bounds__(256) void gru_recurrence(
    const float* __restrict__ whr, const float* __restrict__ whz,
    const float* __restrict__ whn,
    const float* __restrict__ bhr, const float* __restrict__ bhz,
    const float* __restrict__ bhn,
    const float* __restrict__ h0,     // [B,H] initial state
    float* __restrict__ seq,          // [T,B,H]
    float* __restrict__ finals)       // [B,H]
{
    extern __shared__ float sm[];
    float* ht  = sm;                          // [512][64] h transposed (k-major)
    float* wsm = sm + HH * BB;                // [512][16] (12 used: g*4+j)
    ull*   red = (ull*)(sm + HH * BB + HH * WSM_PITCH);  // [16][192]

    const int tid = threadIdx.x;
    const int w   = tid >> 5;                 // warp = k-slice
    const int lane = tid & 31;
    const int btile = lane >> 1;              // 0..15 -> 4 batches
    const int ct = lane & 1;                  // col pair 2*ct, 2*ct+1
    const int jbase = blockIdx.x * 4;

    // activation-phase identity
    const int ab = tid >> 2;                  // batch
    const int aj = tid & 3;                   // local col
    const int jglob = jbase + aj;
    const int act = aj >> 1;                  // which col-pair
    const int ahalf = aj & 1;                 // which half of the pair

    // load weight columns (once): wsm[k][g*4+j] = W_g[k][jbase+j]
    for (int i = tid; i < HH * 12; i += 256) {
        const int k = i / 12;
        const int r = i - k * 12;
        const int g = r >> 2;
        const int j = r & 3;
        const float* src = (g == 0) ? whr : ((g == 1) ? whz : whn);
        wsm[k * WSM_PITCH + r] = src[(size_t)k * HH + jbase + j];
    }
    const float bh_r = bhr[jglob];
    const float bh_z = bhz[jglob];
    const float bh_n = bhn[jglob];

    // stage h0 (b-major in global) transposed into ht[k][b]
    for (int i = tid; i < BB * HH / 4; i += 256) {
        const int b = i >> 7;
        const int k4 = (i & 127) << 2;
        float4 v = *(const float4*)(h0 + (size_t)b * HH + k4);
        ht[(k4 + 0) * BB + b] = v.x; ht[(k4 + 1) * BB + b] = v.y;
        ht[(k4 + 2) * BB + b] = v.z; ht[(k4 + 3) * BB + b] = v.w;
    }
    __syncthreads();

    const float* hbase = ht + btile * 4;
    const float* wbase = wsm + ct * 2;

    for (int t = 0; t < TT; t++) {
        // prefetch gate-x (hidden under dot)
        const int gi = (t * BB + ab) * HH + jglob;
        const float gxr = __ldcs(&g_gx[0][gi]);
        const float gxz = __ldcs(&g_gx[1][gi]);
        const float gxn = __ldcs(&g_gx[2][gi]);

        // ---- dot: 64 k per warp ----
        ull a0r = 0, a1r = 0, a2r = 0, a3r = 0;   // gate r, batches bb=0..3
        ull a0z = 0, a1z = 0, a2z = 0, a3z = 0;
        ull a0n = 0, a1n = 0, a2n = 0, a3n = 0;
#pragma unroll 4
        for (int kk = 0; kk < 64; kk++) {
            const int k = (w << 6) + kk;
            float4 h4 = *(const float4*)(hbase + k * BB);
            ull wr = *(const ull*)(wbase + k * WSM_PITCH + 0);
            ull wz = *(const ull*)(wbase + k * WSM_PITCH + 4);
            ull wn = *(const ull*)(wbase + k * WSM_PITCH + 8);
            ull h0p = pk2(h4.x), h1p = pk2(h4.y), h2p = pk2(h4.z), h3p = pk2(h4.w);
            fma2(a0r, h0p, wr); fma2(a1r, h1p, wr); fma2(a2r, h2p, wr); fma2(a3r, h3p, wr);
            fma2(a0z, h0p, wz); fma2(a1z, h1p, wz); fma2(a2z, h2p, wz); fma2(a3z, h3p, wz);
            fma2(a0n, h0p, wn); fma2(a1n, h1p, wn); fma2(a2n, h2p, wn); fma2(a3n, h3p, wn);
        }

        // store partials: red[w*2+ct][g*64 + b]
        {
            ull* rb = red + (size_t)(w * 2 + ct) * 192;
            const int b0 = btile * 4;
            rb[0 * 64 + b0 + 0] = a0r; rb[0 * 64 + b0 + 1] = a1r;
            rb[0 * 64 + b0 + 2] = a2r; rb[0 * 64 + b0 + 3] = a3r;
            rb[1 * 64 + b0 + 0] = a0z; rb[1 * 64 + b0 + 1] = a1z;
            rb[1 * 64 + b0 + 2] = a2z; rb[1 * 64 + b0 + 3] = a3z;
            rb[2 * 64 + b0 + 0] = a0n; rb[2 * 64 + b0 + 1] = a1n;
            rb[2 * 64 + b0 + 2] = a2n; rb[2 * 64 + b0 + 3] = a3n;
        }
        __syncthreads();

        // ---- reduce over 8 warps + activation (thread = (ab, aj)) ----
        float ar = bh_r, az = bh_z, an = bh_n;
        const float* rf = (const float*)red;
#pragma unroll
        for (int ww = 0; ww < 8; ww++) {
            const size_t base = ((size_t)(ww * 2 + act) * 192) * 2 + ahalf;
            ar += rf[base + (0 * 64 + ab) * 2];
            az += rf[base + (1 * 64 + ab) * 2];
            an += rf[base + (2 * 64 + ab) * 2];
        }

        const float r = 1.f / (1.f + expf(-(gxr + ar)));
        const float z = 1.f / (1.f + expf(-(gxz + az)));
        const float n = tanhf(gxn + r * an);
        const float hp = ht[jglob * BB + ab];
        const float hn_ = (1.f - z) * n + z * hp;

        __stcg(&g_ht[t & 1][jglob * BB + ab], hn_);   // k-major for next step
        seq[gi] = hn_;
        if (t == TT - 1) finals[(size_t)ab * HH + jglob] = hn_;

        grid_sync();   // includes __syncthreads on both sides

        // ---- stage h_t (k-major global -> linear smem copy) ----
        {
            const float4* src4 = (const float4*)g_ht[t & 1];
            float4* dst4 = (float4*)ht;
            for (int i = tid; i < HH * BB / 4; i += 256)
                dst4[i] = __ldcg(&src4[i]);
        }
        __syncthreads();
    }
}

// -------------------------------- launch -----------------------------------------
extern "C" void kernel_launch(void* const* d_in, const int* in_sizes, int n_in,
                              void* d_out, int out_size) {
    const float* x    = (const float*)d_in[0];
    const float* init = (const float*)d_in[1];
    const float* w_ir = (const float*)d_in[2];
    const float* w_hr = (const float*)d_in[3];
    const float* w_iz = (const float*)d_in[4];
    const float* w_hz = (const float*)d_in[5];
    const float* w_in = (const float*)d_in[6];
    const float* w_hn = (const float*)d_in[7];
    const float* b_ir = (const float*)d_in[8];
    const float* b_hr = (const float*)d_in[9];
    const float* b_iz = (const float*)d_in[10];
    const float* b_hz = (const float*)d_in[11];
    const float* b_in = (const float*)d_in[12];
    const float* b_hn = (const float*)d_in[13];

    float* out    = (float*)d_out;
    float* seq    = out;                          // [T,B,H]
    float* finals = out + (size_t)TT * BB * HH;   // [L,B,H]

    const size_t smem_bytes = (size_t)SMEM_FLOATS * sizeof(float);
    static int configured = 0;
    cudaFuncSetAttribute(gru_recurrence,
                         cudaFuncAttributeMaxDynamicSharedMemorySize,
                         (int)smem_bytes);
    (void)configured;

    dim3 ggrid(TT * BB / 128, HH / 128);          // 256 x 4

    for (int l = 0; l < LL; l++) {
        const float* A = (l == 0) ? x : seq;
        const size_t wo = (size_t)l * HH * HH;
        const size_t bo = (size_t)l * HH;

        gemm_xw<<<ggrid, 256>>>(A, w_ir + wo, b_ir + bo, 0);
        gemm_xw<<<ggrid, 256>>>(A, w_iz + wo, b_iz + bo, 1);
        gemm_xw<<<ggrid, 256>>>(A, w_in + wo, b_in + bo, 2);

        gru_recurrence<<<NBLK, 256, smem_bytes>>>(
            w_hr + wo, w_hz + wo, w_hn + wo,
            b_hr + bo, b_hz + bo, b_hn + bo,
            init + (size_t)l * BB * HH,
            seq,
            finals + (size_t)l * BB * HH);
    }
}

// round 3
// speedup vs baseline: 2.2443x; 1.1093x over previous
#include <cuda_runtime.h>
#include <cuda_bf16.h>
#include <math.h>

#define TT   512
#define BB   64
#define HH   512
#define LL   2
#define NBLK 128          // recurrence grid (1 CTA/SM, all co-resident)

typedef unsigned long long ull;

// ---------------- scratch (__device__ globals; allocation-free) ----------------
__device__ float g_gx[3][TT * BB * HH];     // gate-x planes (r,z,n) for current layer
__device__ float g_ht[2][HH * BB];          // double-buffered hidden state, k-major [k][b]
__device__ ull   g_bar;                     // grid barrier ticket (monotonic)

// ---------------- packed fp32x2 helpers (Blackwell) -----------------------------
__device__ __forceinline__ ull pk2(float x) {
    ull r; asm("mov.b64 %0, {%1, %1};" : "=l"(r) : "f"(x)); return r;
}
__device__ __forceinline__ void fma2(ull& acc, ull a, ull b) {
    asm("fma.rn.f32x2 %0, %1, %2, %0;" : "+l"(acc) : "l"(a), "l"(b));
}

// ---------------- h0 transpose: [B,H] b-major -> g_ht[1] [H,B] k-major -----------
__global__ __launch_bounds__(256) void transpose_h0(const float* __restrict__ h0) {
    const int i = blockIdx.x * 256 + threadIdx.x;   // 0..32767
    const int k = i >> 6;
    const int b = i & 63;
    g_ht[1][i] = h0[(size_t)b * HH + k];
}

// ---------------- input-side GEMM: C = A(M,512) * W(512,512) + bias -------------
// BM=128, BN=128, BK=8, 256 threads, 8x8 per-thread tile, f32x2 accumulation.
// blockIdx.z selects the gate (0=r, 1=z, 2=n).
__global__ __launch_bounds__(256) void gemm_xw(const float* __restrict__ A,
                                               const float* __restrict__ W0,
                                               const float* __restrict__ W1,
                                               const float* __restrict__ W2,
                                               const float* __restrict__ bias0,
                                               const float* __restrict__ bias1,
                                               const float* __restrict__ bias2) {
    __shared__ float As[2][8][128];
    __shared__ float Ws[2][8][128];

    const int gate = blockIdx.z;
    const float* W    = (gate == 0) ? W0 : ((gate == 1) ? W1 : W2);
    const float* bias = (gate == 0) ? bias0 : ((gate == 1) ? bias1 : bias2);

    const int bm = blockIdx.x * 128;
    const int bn = blockIdx.y * 128;
    const int tid = threadIdx.x;

    const int ar = tid >> 1;          // 0..127 (A row)
    const int ak = (tid & 1) << 2;    // 0,4
    const int wk = tid >> 5;          // 0..7
    const int wn = (tid & 31) << 2;   // 0..124

    const int tm = (tid >> 4) << 3;
    const int tn = (tid & 15) << 3;

    ull acc[8][4];
#pragma unroll
    for (int i = 0; i < 8; i++)
#pragma unroll
        for (int j = 0; j < 4; j++) acc[i][j] = 0ull;

    {
        float4 va = *(const float4*)(A + (size_t)(bm + ar) * HH + ak);
        As[0][ak + 0][ar] = va.x; As[0][ak + 1][ar] = va.y;
        As[0][ak + 2][ar] = va.z; As[0][ak + 3][ar] = va.w;
        *(float4*)&Ws[0][wk][wn] = *(const float4*)(W + (size_t)wk * HH + bn + wn);
    }
    __syncthreads();

    for (int kt = 0; kt < HH; kt += 8) {
        const int buf = (kt >> 3) & 1;
        float4 pa, pw;
        const bool more = (kt + 8) < HH;
        if (more) {
            pa = *(const float4*)(A + (size_t)(bm + ar) * HH + kt + 8 + ak);
            pw = *(const float4*)(W + (size_t)(kt + 8 + wk) * HH + bn + wn);
        }
#pragma unroll
        for (int k = 0; k < 8; k++) {
            float4 a0 = *(const float4*)&As[buf][k][tm];
            float4 a1 = *(const float4*)&As[buf][k][tm + 4];
            ulonglong2 b0 = *(const ulonglong2*)&Ws[buf][k][tn];
            ulonglong2 b1 = *(const ulonglong2*)&Ws[buf][k][tn + 4];
            ull bp[4] = {b0.x, b0.y, b1.x, b1.y};
            float am[8] = {a0.x, a0.y, a0.z, a0.w, a1.x, a1.y, a1.z, a1.w};
#pragma unroll
            for (int i = 0; i < 8; i++) {
                ull ap = pk2(am[i]);
#pragma unroll
                for (int j = 0; j < 4; j++) fma2(acc[i][j], ap, bp[j]);
            }
        }
        if (more) {
            const int nb = buf ^ 1;
            As[nb][ak + 0][ar] = pa.x; As[nb][ak + 1][ar] = pa.y;
            As[nb][ak + 2][ar] = pa.z; As[nb][ak + 3][ar] = pa.w;
            *(float4*)&Ws[nb][wk][wn] = pw;
        }
        __syncthreads();
    }

    float* C = g_gx[0] + (size_t)gate * (TT * BB * HH);
#pragma unroll
    for (int i = 0; i < 8; i++) {
        const size_t row = (size_t)(bm + tm + i) * HH;
#pragma unroll
        for (int j = 0; j < 4; j++) {
            const int col = bn + tn + 2 * j;
            float2 v = *(float2*)&acc[i][j];
            v.x += bias[col]; v.y += bias[col + 1];
            *(float2*)&C[row + col] = v;
        }
    }
}

// ---------------- grid barrier ---------------------------------------------------
__device__ __forceinline__ void grid_sync() {
    __syncthreads();
    if (threadIdx.x == 0) {
        __threadfence();
        ull t = atomicAdd(&g_bar, 1ull) + 1ull;
        ull target = ((t - 1ull) / NBLK + 1ull) * (ull)NBLK;
        volatile ull* vb = &g_bar;
        while (*vb < target) { }
        __threadfence();
    }
    __syncthreads();
}

// ---------------- persistent recurrence ------------------------------------------
// 128 CTAs x 256 threads. CTA owns 4 hidden columns (3 gates each).
// Dot: warp = 64-k slice, pipelined 4x16k chunks (LDG next chunk under fma of
// current). lane: btile = lane>>1 (4 batches), ct = lane&1 (col pair).
#define WSM_PITCH 16
#define SMEM_FLOATS (HH * BB + HH * WSM_PITCH + 16 * 192 * 2)

__global__ __launch_bounds__(256) void gru_recurrence(
    const float* __restrict__ whr, const float* __restrict__ whz,
    const float* __restrict__ whn,
    const float* __restrict__ bhr, const float* __restrict__ bhz,
    const float* __restrict__ bhn,
    float* __restrict__ seq,          // [T,B,H]
    float* __restrict__ finals)       // [B,H]
{
    extern __shared__ float sm[];
    float* ht  = sm;                          // [512][64] h (k-major)
    float* wsm = sm + HH * BB;                // [512][16] (12 used: g*4+j)
    ull*   red = (ull*)(sm + HH * BB + HH * WSM_PITCH);  // [16][192]

    const int tid = threadIdx.x;
    const int w   = tid >> 5;                 // warp = k-slice
    const int lane = tid & 31;
    const int btile = lane >> 1;              // 0..15 -> 4 batches
    const int ct = lane & 1;                  // col pair 2*ct, 2*ct+1
    const int jbase = blockIdx.x * 4;

    // activation-phase identity
    const int ab = tid >> 2;                  // batch
    const int aj = tid & 3;                   // local col
    const int jglob = jbase + aj;
    const int act = aj >> 1;
    const int ahalf = aj & 1;

    // load weight columns (once): wsm[k][g*4+j] = W_g[k][jbase+j]
    for (int i = tid; i < HH * 12; i += 256) {
        const int k = i / 12;
        const int r = i - k * 12;
        const int g = r >> 2;
        const int j = r & 3;
        const float* src = (g == 0) ? whr : ((g == 1) ? whz : whn);
        wsm[k * WSM_PITCH + r] = src[(size_t)k * HH + jbase + j];
    }
    const float bh_r = bhr[jglob];
    const float bh_z = bhz[jglob];
    const float bh_n = bhn[jglob];
    __syncthreads();

    const float* hbase = ht + btile * 4;
    const float* wbase = wsm + ct * 2;
    // warp's slice: k in [w*64, w*64+64); chunk c: k in [w*64+c*16, +16)
    // chunk floats: 16*64 = 1024 = 256 float4; lane handles f = i*32+lane, i<8
    float4* ht4 = (float4*)ht;
    const int slice_f4 = w * (64 * BB / 4);   // float4 offset of slice start

    for (int t = 0; t < TT; t++) {
        // prefetch gate-x (hidden under dot)
        const int gi = (t * BB + ab) * HH + jglob;
        const float gxr = __ldcs(&g_gx[0][gi]);
        const float gxz = __ldcs(&g_gx[1][gi]);
        const float gxn = __ldcs(&g_gx[2][gi]);

        const float4* src4 = (const float4*)g_ht[(t - 1) & 1];

        ull a0r = 0, a1r = 0, a2r = 0, a3r = 0;
        ull a0z = 0, a1z = 0, a2z = 0, a3z = 0;
        ull a0n = 0, a1n = 0, a2n = 0, a3n = 0;

        float4 pf[2][8];
        // preload chunk 0
#pragma unroll
        for (int i = 0; i < 8; i++)
            pf[0][i] = __ldcg(&src4[slice_f4 + i * 32 + lane]);

#pragma unroll
        for (int c = 0; c < 4; c++) {
            if (c < 3) {
#pragma unroll
                for (int i = 0; i < 8; i++)
                    pf[(c + 1) & 1][i] =
                        __ldcg(&src4[slice_f4 + (c + 1) * 256 + i * 32 + lane]);
            }
            // STS chunk c into smem slice
#pragma unroll
            for (int i = 0; i < 8; i++)
                ht4[slice_f4 + c * 256 + i * 32 + lane] = pf[c & 1][i];
            __syncwarp();

            // dot over chunk c (16 k)
#pragma unroll
            for (int kk = 0; kk < 16; kk++) {
                const int k = (w << 6) + (c << 4) + kk;
                float4 h4 = *(const float4*)(hbase + k * BB);
                ull wr = *(const ull*)(wbase + k * WSM_PITCH + 0);
                ull wz = *(const ull*)(wbase + k * WSM_PITCH + 4);
                ull wn = *(const ull*)(wbase + k * WSM_PITCH + 8);
                ull h0p = pk2(h4.x), h1p = pk2(h4.y), h2p = pk2(h4.z), h3p = pk2(h4.w);
                fma2(a0r, h0p, wr); fma2(a1r, h1p, wr); fma2(a2r, h2p, wr); fma2(a3r, h3p, wr);
                fma2(a0z, h0p, wz); fma2(a1z, h1p, wz); fma2(a2z, h2p, wz); fma2(a3z, h3p, wz);
                fma2(a0n, h0p, wn); fma2(a1n, h1p, wn); fma2(a2n, h2p, wn); fma2(a3n, h3p, wn);
            }
        }

        // store partials: red[w*2+ct][g*64 + b]
        {
            ull* rb = red + (size_t)(w * 2 + ct) * 192;
            const int b0 = btile * 4;
            rb[0 * 64 + b0 + 0] = a0r; rb[0 * 64 + b0 + 1] = a1r;
            rb[0 * 64 + b0 + 2] = a2r; rb[0 * 64 + b0 + 3] = a3r;
            rb[1 * 64 + b0 + 0] = a0z; rb[1 * 64 + b0 + 1] = a1z;
            rb[1 * 64 + b0 + 2] = a2z; rb[1 * 64 + b0 + 3] = a3z;
            rb[2 * 64 + b0 + 0] = a0n; rb[2 * 64 + b0 + 1] = a1n;
            rb[2 * 64 + b0 + 2] = a2n; rb[2 * 64 + b0 + 3] = a3n;
        }
        __syncthreads();

        // ---- reduce over 8 warps + activation (thread = (ab, aj)) ----
        float ar = bh_r, az = bh_z, an = bh_n;
        const float* rf = (const float*)red;
#pragma unroll
        for (int ww = 0; ww < 8; ww++) {
            const size_t base = ((size_t)(ww * 2 + act) * 192) * 2 + ahalf;
            ar += rf[base + (0 * 64 + ab) * 2];
            az += rf[base + (1 * 64 + ab) * 2];
            an += rf[base + (2 * 64 + ab) * 2];
        }

        const float r = 1.f / (1.f + expf(-(gxr + ar)));
        const float z = 1.f / (1.f + expf(-(gxz + az)));
        const float n = tanhf(gxn + r * an);
        const float hp = ht[jglob * BB + ab];
        const float hn_ = (1.f - z) * n + z * hp;

        __stcg(&g_ht[t & 1][jglob * BB + ab], hn_);   // k-major for next step
        seq[gi] = hn_;
        if (t == TT - 1) finals[(size_t)ab * HH + jglob] = hn_;

        grid_sync();
    }
}

// -------------------------------- launch -----------------------------------------
extern "C" void kernel_launch(void* const* d_in, const int* in_sizes, int n_in,
                              void* d_out, int out_size) {
    const float* x    = (const float*)d_in[0];
    const float* init = (const float*)d_in[1];
    const float* w_ir = (const float*)d_in[2];
    const float* w_hr = (const float*)d_in[3];
    const float* w_iz = (const float*)d_in[4];
    const float* w_hz = (const float*)d_in[5];
    const float* w_in = (const float*)d_in[6];
    const float* w_hn = (const float*)d_in[7];
    const float* b_ir = (const float*)d_in[8];
    const float* b_hr = (const float*)d_in[9];
    const float* b_iz = (const float*)d_in[10];
    const float* b_hz = (const float*)d_in[11];
    const float* b_in = (const float*)d_in[12];
    const float* b_hn = (const float*)d_in[13];

    float* out    = (float*)d_out;
    float* seq    = out;                          // [T,B,H]
    float* finals = out + (size_t)TT * BB * HH;   // [L,B,H]

    const size_t smem_bytes = (size_t)SMEM_FLOATS * sizeof(float);
    cudaFuncSetAttribute(gru_recurrence,
                         cudaFuncAttributeMaxDynamicSharedMemorySize,
                         (int)smem_bytes);

    dim3 ggrid(TT * BB / 128, HH / 128, 3);       // 256 x 4 x 3

    for (int l = 0; l < LL; l++) {
        const float* A = (l == 0) ? x : seq;
        const size_t wo = (size_t)l * HH * HH;
        const size_t bo = (size_t)l * HH;

        gemm_xw<<<ggrid, 256>>>(A,
                                w_ir + wo, w_iz + wo, w_in + wo,
                                b_ir + bo, b_iz + bo, b_in + bo);

        transpose_h0<<<HH * BB / 256, 256>>>(init + (size_t)l * BB * HH);

        gru_recurrence<<<NBLK, 256, smem_bytes>>>(
            w_hr + wo, w_hz + wo, w_hn + wo,
            b_hr + bo, b_hz + bo, b_hn + bo,
            seq,
            finals + (size_t)l * BB * HH);
    }
}

// round 4
// speedup vs baseline: 2.2473x; 1.0013x over previous
#include <cuda_runtime.h>
#include <cuda_bf16.h>
#include <math.h>

#define TT   512
#define BB   64
#define HH   512
#define LL   2
#define NBLK 128          // recurrence grid (1 CTA/SM, all co-resident)

typedef unsigned long long ull;

// ---------------- scratch (__device__ globals; allocation-free) ----------------
__device__ float g_gx[3][TT * BB * HH];     // gate-x planes (r,z,n) for current layer
__device__ float g_ht[2][HH * BB];          // double-buffered hidden state, k-major [k][b]
__device__ ull   g_bar;                     // grid barrier ticket (monotonic)

// ---------------- packed fp32x2 helpers (Blackwell) -----------------------------
__device__ __forceinline__ ull pk2(float x) {
    ull r; asm("mov.b64 %0, {%1, %1};" : "=l"(r) : "f"(x)); return r;
}
__device__ __forceinline__ void fma2(ull& acc, ull a, ull b) {
    asm("fma.rn.f32x2 %0, %1, %2, %0;" : "+l"(acc) : "l"(a), "l"(b));
}

// ---------------- h0 transpose: [B,H] b-major -> g_ht[1] [H,B] k-major -----------
__global__ __launch_bounds__(256) void transpose_h0(const float* __restrict__ h0) {
    const int i = blockIdx.x * 256 + threadIdx.x;   // 0..32767
    const int k = i >> 6;
    const int b = i & 63;
    g_ht[1][i] = h0[(size_t)b * HH + k];
}

// ---------------- input-side GEMM: C = A(M,512) * W(512,512) + bias -------------
// BM=128, BN=128, BK=8, 256 threads, 8x8 per-thread tile, f32x2 accumulation.
// blockIdx.z selects the gate (0=r, 1=z, 2=n).
__global__ __launch_bounds__(256) void gemm_xw(const float* __restrict__ A,
                                               const float* __restrict__ W0,
                                               const float* __restrict__ W1,
                                               const float* __restrict__ W2,
                                               const float* __restrict__ bias0,
                                               const float* __restrict__ bias1,
                                               const float* __restrict__ bias2) {
    __shared__ float As[2][8][128];
    __shared__ float Ws[2][8][128];

    const int gate = blockIdx.z;
    const float* W    = (gate == 0) ? W0 : ((gate == 1) ? W1 : W2);
    const float* bias = (gate == 0) ? bias0 : ((gate == 1) ? bias1 : bias2);

    const int bm = blockIdx.x * 128;
    const int bn = blockIdx.y * 128;
    const int tid = threadIdx.x;

    const int ar = tid >> 1;          // 0..127 (A row)
    const int ak = (tid & 1) << 2;    // 0,4
    const int wk = tid >> 5;          // 0..7
    const int wn = (tid & 31) << 2;   // 0..124

    const int tm = (tid >> 4) << 3;
    const int tn = (tid & 15) << 3;

    ull acc[8][4];
#pragma unroll
    for (int i = 0; i < 8; i++)
#pragma unroll
        for (int j = 0; j < 4; j++) acc[i][j] = 0ull;

    {
        float4 va = *(const float4*)(A + (size_t)(bm + ar) * HH + ak);
        As[0][ak + 0][ar] = va.x; As[0][ak + 1][ar] = va.y;
        As[0][ak + 2][ar] = va.z; As[0][ak + 3][ar] = va.w;
        *(float4*)&Ws[0][wk][wn] = *(const float4*)(W + (size_t)wk * HH + bn + wn);
    }
    __syncthreads();

    for (int kt = 0; kt < HH; kt += 8) {
        const int buf = (kt >> 3) & 1;
        float4 pa, pw;
        const bool more = (kt + 8) < HH;
        if (more) {
            pa = *(const float4*)(A + (size_t)(bm + ar) * HH + kt + 8 + ak);
            pw = *(const float4*)(W + (size_t)(kt + 8 + wk) * HH + bn + wn);
        }
#pragma unroll
        for (int k = 0; k < 8; k++) {
            float4 a0 = *(const float4*)&As[buf][k][tm];
            float4 a1 = *(const float4*)&As[buf][k][tm + 4];
            ulonglong2 b0 = *(const ulonglong2*)&Ws[buf][k][tn];
            ulonglong2 b1 = *(const ulonglong2*)&Ws[buf][k][tn + 4];
            ull bp[4] = {b0.x, b0.y, b1.x, b1.y};
            float am[8] = {a0.x, a0.y, a0.z, a0.w, a1.x, a1.y, a1.z, a1.w};
#pragma unroll
            for (int i = 0; i < 8; i++) {
                ull ap = pk2(am[i]);
#pragma unroll
                for (int j = 0; j < 4; j++) fma2(acc[i][j], ap, bp[j]);
            }
        }
        if (more) {
            const int nb = buf ^ 1;
            As[nb][ak + 0][ar] = pa.x; As[nb][ak + 1][ar] = pa.y;
            As[nb][ak + 2][ar] = pa.z; As[nb][ak + 3][ar] = pa.w;
            *(float4*)&Ws[nb][wk][wn] = pw;
        }
        __syncthreads();
    }

    float* C = g_gx[0] + (size_t)gate * (TT * BB * HH);
#pragma unroll
    for (int i = 0; i < 8; i++) {
        const size_t row = (size_t)(bm + tm + i) * HH;
#pragma unroll
        for (int j = 0; j < 4; j++) {
            const int col = bn + tn + 2 * j;
            float2 v = *(float2*)&acc[i][j];
            v.x += bias[col]; v.y += bias[col + 1];
            *(float2*)&C[row + col] = v;
        }
    }
}

// ---------------- grid barrier ---------------------------------------------------
__device__ __forceinline__ void grid_sync() {
    __syncthreads();
    if (threadIdx.x == 0) {
        __threadfence();
        ull t = atomicAdd(&g_bar, 1ull) + 1ull;
        ull target = ((t - 1ull) / NBLK + 1ull) * (ull)NBLK;
        volatile ull* vb = &g_bar;
        while (*vb < target) { }
        __threadfence();
    }
    __syncthreads();
}

// ---------------- persistent recurrence ------------------------------------------
// 128 CTAs x 256 threads. CTA owns 4 hidden columns (3 gates each).
// Dot: warp = 64-k slice, pipelined 4x16k chunks (LDG next chunk under fma of
// current). lane: btile = lane>>1 (4 batches), ct = lane&1 (col pair).
#define WSM_PITCH 16
#define SMEM_FLOATS (HH * BB + HH * WSM_PITCH + 16 * 192 * 2)

__global__ __launch_bounds__(256) void gru_recurrence(
    const float* __restrict__ whr, const float* __restrict__ whz,
    const float* __restrict__ whn,
    const float* __restrict__ bhr, const float* __restrict__ bhz,
    const float* __restrict__ bhn,
    float* __restrict__ seq,          // [T,B,H]
    float* __restrict__ finals)       // [B,H]
{
    extern __shared__ float sm[];
    float* ht  = sm;                          // [512][64] h (k-major)
    float* wsm = sm + HH * BB;                // [512][16] (12 used: g*4+j)
    ull*   red = (ull*)(sm + HH * BB + HH * WSM_PITCH);  // [16][192]

    const int tid = threadIdx.x;
    const int w   = tid >> 5;                 // warp = k-slice
    const int lane = tid & 31;
    const int btile = lane >> 1;              // 0..15 -> 4 batches
    const int ct = lane & 1;                  // col pair 2*ct, 2*ct+1
    const int jbase = blockIdx.x * 4;

    // activation-phase identity
    const int ab = tid >> 2;                  // batch
    const int aj = tid & 3;                   // local col
    const int jglob = jbase + aj;
    const int act = aj >> 1;
    const int ahalf = aj & 1;

    // load weight columns (once): wsm[k][g*4+j] = W_g[k][jbase+j]
    for (int i = tid; i < HH * 12; i += 256) {
        const int k = i / 12;
        const int r = i - k * 12;
        const int g = r >> 2;
        const int j = r & 3;
        const float* src = (g == 0) ? whr : ((g == 1) ? whz : whn);
        wsm[k * WSM_PITCH + r] = src[(size_t)k * HH + jbase + j];
    }
    const float bh_r = bhr[jglob];
    const float bh_z = bhz[jglob];
    const float bh_n = bhn[jglob];
    __syncthreads();

    const float* hbase = ht + btile * 4;
    const float* wbase = wsm + ct * 2;
    // warp's slice: k in [w*64, w*64+64); chunk c: k in [w*64+c*16, +16)
    // chunk floats: 16*64 = 1024 = 256 float4; lane handles f = i*32+lane, i<8
    float4* ht4 = (float4*)ht;
    const int slice_f4 = w * (64 * BB / 4);   // float4 offset of slice start

    for (int t = 0; t < TT; t++) {
        // prefetch gate-x (hidden under dot)
        const int gi = (t * BB + ab) * HH + jglob;
        const float gxr = __ldcs(&g_gx[0][gi]);
        const float gxz = __ldcs(&g_gx[1][gi]);
        const float gxn = __ldcs(&g_gx[2][gi]);

        const float4* src4 = (const float4*)g_ht[(t - 1) & 1];

        ull a0r = 0, a1r = 0, a2r = 0, a3r = 0;
        ull a0z = 0, a1z = 0, a2z = 0, a3z = 0;
        ull a0n = 0, a1n = 0, a2n = 0, a3n = 0;

        float4 pf[2][8];
        // preload chunk 0
#pragma unroll
        for (int i = 0; i < 8; i++)
            pf[0][i] = __ldcg(&src4[slice_f4 + i * 32 + lane]);

#pragma unroll
        for (int c = 0; c < 4; c++) {
            if (c < 3) {
#pragma unroll
                for (int i = 0; i < 8; i++)
                    pf[(c + 1) & 1][i] =
                        __ldcg(&src4[slice_f4 + (c + 1) * 256 + i * 32 + lane]);
            }
            // STS chunk c into smem slice
#pragma unroll
            for (int i = 0; i < 8; i++)
                ht4[slice_f4 + c * 256 + i * 32 + lane] = pf[c & 1][i];
            __syncwarp();

            // dot over chunk c (16 k)
#pragma unroll
            for (int kk = 0; kk < 16; kk++) {
                const int k = (w << 6) + (c << 4) + kk;
                float4 h4 = *(const float4*)(hbase + k * BB);
                ull wr = *(const ull*)(wbase + k * WSM_PITCH + 0);
                ull wz = *(const ull*)(wbase + k * WSM_PITCH + 4);
                ull wn = *(const ull*)(wbase + k * WSM_PITCH + 8);
                ull h0p = pk2(h4.x), h1p = pk2(h4.y), h2p = pk2(h4.z), h3p = pk2(h4.w);
                fma2(a0r, h0p, wr); fma2(a1r, h1p, wr); fma2(a2r, h2p, wr); fma2(a3r, h3p, wr);
                fma2(a0z, h0p, wz); fma2(a1z, h1p, wz); fma2(a2z, h2p, wz); fma2(a3z, h3p, wz);
                fma2(a0n, h0p, wn); fma2(a1n, h1p, wn); fma2(a2n, h2p, wn); fma2(a3n, h3p, wn);
            }
        }

        // store partials: red[w*2+ct][g*64 + b]
        {
            ull* rb = red + (size_t)(w * 2 + ct) * 192;
            const int b0 = btile * 4;
            rb[0 * 64 + b0 + 0] = a0r; rb[0 * 64 + b0 + 1] = a1r;
            rb[0 * 64 + b0 + 2] = a2r; rb[0 * 64 + b0 + 3] = a3r;
            rb[1 * 64 + b0 + 0] = a0z; rb[1 * 64 + b0 + 1] = a1z;
            rb[1 * 64 + b0 + 2] = a2z; rb[1 * 64 + b0 + 3] = a3z;
            rb[2 * 64 + b0 + 0] = a0n; rb[2 * 64 + b0 + 1] = a1n;
            rb[2 * 64 + b0 + 2] = a2n; rb[2 * 64 + b0 + 3] = a3n;
        }
        __syncthreads();

        // ---- reduce over 8 warps + activation (thread = (ab, aj)) ----
        float ar = bh_r, az = bh_z, an = bh_n;
        const float* rf = (const float*)red;
#pragma unroll
        for (int ww = 0; ww < 8; ww++) {
            const size_t base = ((size_t)(ww * 2 + act) * 192) * 2 + ahalf;
            ar += rf[base + (0 * 64 + ab) * 2];
            az += rf[base + (1 * 64 + ab) * 2];
            an += rf[base + (2 * 64 + ab) * 2];
        }

        const float r = 1.f / (1.f + expf(-(gxr + ar)));
        const float z = 1.f / (1.f + expf(-(gxz + az)));
        const float n = tanhf(gxn + r * an);
        const float hp = ht[jglob * BB + ab];
        const float hn_ = (1.f - z) * n + z * hp;

        __stcg(&g_ht[t & 1][jglob * BB + ab], hn_);   // k-major for next step
        seq[gi] = hn_;
        if (t == TT - 1) finals[(size_t)ab * HH + jglob] = hn_;

        grid_sync();
    }
}

// -------------------------------- launch -----------------------------------------
extern "C" void kernel_launch(void* const* d_in, const int* in_sizes, int n_in,
                              void* d_out, int out_size) {
    const float* x    = (const float*)d_in[0];
    const float* init = (const float*)d_in[1];
    const float* w_ir = (const float*)d_in[2];
    const float* w_hr = (const float*)d_in[3];
    const float* w_iz = (const float*)d_in[4];
    const float* w_hz = (const float*)d_in[5];
    const float* w_in = (const float*)d_in[6];
    const float* w_hn = (const float*)d_in[7];
    const float* b_ir = (const float*)d_in[8];
    const float* b_hr = (const float*)d_in[9];
    const float* b_iz = (const float*)d_in[10];
    const float* b_hz = (const float*)d_in[11];
    const float* b_in = (const float*)d_in[12];
    const float* b_hn = (const float*)d_in[13];

    float* out    = (float*)d_out;
    float* seq    = out;                          // [T,B,H]
    float* finals = out + (size_t)TT * BB * HH;   // [L,B,H]

    const size_t smem_bytes = (size_t)SMEM_FLOATS * sizeof(float);
    cudaFuncSetAttribute(gru_recurrence,
                         cudaFuncAttributeMaxDynamicSharedMemorySize,
                         (int)smem_bytes);

    dim3 ggrid(TT * BB / 128, HH / 128, 3);       // 256 x 4 x 3

    for (int l = 0; l < LL; l++) {
        const float* A = (l == 0) ? x : seq;
        const size_t wo = (size_t)l * HH * HH;
        const size_t bo = (size_t)l * HH;

        gemm_xw<<<ggrid, 256>>>(A,
                                w_ir + wo, w_iz + wo, w_in + wo,
                                b_ir + bo, b_iz + bo, b_in + bo);

        transpose_h0<<<HH * BB / 256, 256>>>(init + (size_t)l * BB * HH);

        gru_recurrence<<<NBLK, 256, smem_bytes>>>(
            w_hr + wo, w_hz + wo, w_hn + wo,
            b_hr + bo, b_hz + bo, b_hn + bo,
            seq,
            finals + (size_t)l * BB * HH);
    }
}

// round 5
// speedup vs baseline: 2.4852x; 1.1058x over previous
#include <cuda_runtime.h>
#include <cuda_bf16.h>
#include <math.h>
#include <stdint.h>

#define TT   512
#define BB   64
#define HH   512
#define LL   2
#define NBLK 128          // recurrence grid (1 CTA/SM, all co-resident)
#define RTH  512          // recurrence threads

typedef unsigned long long ull;

// ---------------- scratch (__device__ globals; allocation-free) ----------------
__device__ float g_gx[3][TT * BB * HH];     // gate-x planes (r,z,n) for current layer
__device__ float g_ht[2][HH * BB];          // double-buffered hidden state, k-major [k][b]
__device__ ull   g_bar;                     // grid barrier ticket (monotonic)

// ---------------- packed fp32x2 helpers (Blackwell) -----------------------------
__device__ __forceinline__ ull pk2(float x) {
    ull r; asm("mov.b64 %0, {%1, %1};" : "=l"(r) : "f"(x)); return r;
}
__device__ __forceinline__ void fma2(ull& acc, ull a, ull b) {
    asm("fma.rn.f32x2 %0, %1, %2, %0;" : "+l"(acc) : "l"(a), "l"(b));
}

// tf32 round-to-nearest of an fp32 (bits usable by mma.tf32)
__device__ __forceinline__ float tf32r(float x) {
    uint32_t y;
    asm("cvt.rna.tf32.f32 %0, %1;" : "=r"(y) : "f"(x));
    return __uint_as_float(y);
}

__device__ __forceinline__ void mma_tf32(float c[4], const uint32_t a[4],
                                         const uint32_t b[2]) {
    asm volatile(
        "mma.sync.aligned.m16n8k8.row.col.f32.tf32.tf32.f32 "
        "{%0,%1,%2,%3}, {%4,%5,%6,%7}, {%8,%9}, {%0,%1,%2,%3};"
        : "+f"(c[0]), "+f"(c[1]), "+f"(c[2]), "+f"(c[3])
        : "r"(a[0]), "r"(a[1]), "r"(a[2]), "r"(a[3]), "r"(b[0]), "r"(b[1]));
}

// ---------------- h0 transpose: [B,H] b-major -> g_ht[1] [H,B] k-major -----------
__global__ __launch_bounds__(256) void transpose_h0(const float* __restrict__ h0) {
    const int i = blockIdx.x * 256 + threadIdx.x;   // 0..32767
    const int k = i >> 6;
    const int b = i & 63;
    g_ht[1][i] = h0[(size_t)b * HH + k];
}

// ---------------- input GEMM (tensor cores, tf32) --------------------------------
// C = A(M,512) * W(512,512) + bias ; BM=128, BN=128, BK=32, 256 thr (8 warps),
// warp tile 64x32 (m16n8k8 x 4m x 4n). blockIdx.z = gate.
#define GPITCH 132
#define GEMM_SMEM_FLOATS (2 * 32 * GPITCH * 2)

__global__ __launch_bounds__(256) void gemm_xw_mma(const float* __restrict__ A,
                                                   const float* __restrict__ W0,
                                                   const float* __restrict__ W1,
                                                   const float* __restrict__ W2,
                                                   const float* __restrict__ bias0,
                                                   const float* __restrict__ bias1,
                                                   const float* __restrict__ bias2) {
    extern __shared__ float gsm[];
    float* Asm = gsm;                         // [2][32][GPITCH] (k-major: [k][m])
    float* Bsm = gsm + 2 * 32 * GPITCH;       // [2][32][GPITCH] ([k][n])
#define AS(b, k, m) Asm[((b) * 32 + (k)) * GPITCH + (m)]
#define BS(b, k, n) Bsm[((b) * 32 + (k)) * GPITCH + (n)]

    const int gate = blockIdx.z;
    const float* W    = (gate == 0) ? W0 : ((gate == 1) ? W1 : W2);
    const float* bias = (gate == 0) ? bias0 : ((gate == 1) ? bias1 : bias2);

    const int bm = blockIdx.x * 128;
    const int bn = blockIdx.y * 128;
    const int tid = threadIdx.x;
    const int lane = tid & 31;
    const int wid = tid >> 5;
    const int warp_m = wid >> 2;              // 0..1
    const int warp_n = wid & 3;               // 0..3

    // A loader: row = tid>>1, k-half = (tid&1)*16, 4 float4 per thread
    const int arow = tid >> 1;
    const int ahalf = (tid & 1) << 4;
    // W loader: 4 float4: k = (tid>>5) + s*8, n4 = (tid&31)*4
    const int wk0 = tid >> 5;
    const int wn4 = (tid & 31) << 2;

    float acc[4][4][4];
#pragma unroll
    for (int mt = 0; mt < 4; mt++)
#pragma unroll
        for (int nt = 0; nt < 4; nt++)
#pragma unroll
            for (int i = 0; i < 4; i++) acc[mt][nt][i] = 0.f;

    // preload tile 0
#pragma unroll
    for (int q = 0; q < 4; q++) {
        float4 v = *(const float4*)(A + (size_t)(bm + arow) * HH + ahalf + q * 4);
        AS(0, ahalf + q * 4 + 0, arow) = tf32r(v.x);
        AS(0, ahalf + q * 4 + 1, arow) = tf32r(v.y);
        AS(0, ahalf + q * 4 + 2, arow) = tf32r(v.z);
        AS(0, ahalf + q * 4 + 3, arow) = tf32r(v.w);
    }
#pragma unroll
    for (int s = 0; s < 4; s++) {
        float4 v = *(const float4*)(W + (size_t)(wk0 + s * 8) * HH + bn + wn4);
        v.x = tf32r(v.x); v.y = tf32r(v.y); v.z = tf32r(v.z); v.w = tf32r(v.w);
        *(float4*)&BS(0, wk0 + s * 8, wn4) = v;
    }
    __syncthreads();

    const int r = lane >> 2;                  // 0..7
    const int cq = lane & 3;                  // 0..3
    const int mrow = warp_m * 64 + r;
    const int nbase = warp_n * 32 + r;

    for (int kt = 0; kt < HH; kt += 32) {
        const int buf = (kt >> 5) & 1;
        const bool more = (kt + 32) < HH;
        float4 pa[4], pw[4];
        if (more) {
#pragma unroll
            for (int q = 0; q < 4; q++)
                pa[q] = *(const float4*)(A + (size_t)(bm + arow) * HH + kt + 32 + ahalf + q * 4);
#pragma unroll
            for (int s = 0; s < 4; s++)
                pw[s] = *(const float4*)(W + (size_t)(kt + 32 + wk0 + s * 8) * HH + bn + wn4);
        }

#pragma unroll
        for (int ks = 0; ks < 4; ks++) {
            const int kk = ks * 8;
            uint32_t af[4][4];
#pragma unroll
            for (int mt = 0; mt < 4; mt++) {
                af[mt][0] = __float_as_uint(AS(buf, kk + cq,     mrow + mt * 16));
                af[mt][1] = __float_as_uint(AS(buf, kk + cq,     mrow + mt * 16 + 8));
                af[mt][2] = __float_as_uint(AS(buf, kk + cq + 4, mrow + mt * 16));
                af[mt][3] = __float_as_uint(AS(buf, kk + cq + 4, mrow + mt * 16 + 8));
            }
            uint32_t bf[4][2];
#pragma unroll
            for (int nt = 0; nt < 4; nt++) {
                bf[nt][0] = __float_as_uint(BS(buf, kk + cq,     nbase + nt * 8));
                bf[nt][1] = __float_as_uint(BS(buf, kk + cq + 4, nbase + nt * 8));
            }
#pragma unroll
            for (int mt = 0; mt < 4; mt++)
#pragma unroll
                for (int nt = 0; nt < 4; nt++)
                    mma_tf32(acc[mt][nt], af[mt], bf[nt]);
        }

        if (more) {
            const int nb = buf ^ 1;
#pragma unroll
            for (int q = 0; q < 4; q++) {
                AS(nb, ahalf + q * 4 + 0, arow) = tf32r(pa[q].x);
                AS(nb, ahalf + q * 4 + 1, arow) = tf32r(pa[q].y);
                AS(nb, ahalf + q * 4 + 2, arow) = tf32r(pa[q].z);
                AS(nb, ahalf + q * 4 + 3, arow) = tf32r(pa[q].w);
            }
#pragma unroll
            for (int s = 0; s < 4; s++) {
                float4 v = pw[s];
                v.x = tf32r(v.x); v.y = tf32r(v.y); v.z = tf32r(v.z); v.w = tf32r(v.w);
                *(float4*)&BS(nb, wk0 + s * 8, wn4) = v;
            }
        }
        __syncthreads();
    }

    // epilogue
    float* C = g_gx[0] + (size_t)gate * ((size_t)TT * BB * HH);
    const int m0 = bm + warp_m * 64 + r;
    const int n0 = bn + warp_n * 32 + 2 * cq;
#pragma unroll
    for (int nt = 0; nt < 4; nt++) {
        const int col = n0 + nt * 8;
        const float b0 = bias[col];
        const float b1 = bias[col + 1];
#pragma unroll
        for (int mt = 0; mt < 4; mt++) {
            const int row0 = m0 + mt * 16;
            float2 v0 = make_float2(acc[mt][nt][0] + b0, acc[mt][nt][1] + b1);
            float2 v1 = make_float2(acc[mt][nt][2] + b0, acc[mt][nt][3] + b1);
            *(float2*)&C[(size_t)row0 * HH + col] = v0;
            *(float2*)&C[(size_t)(row0 + 8) * HH + col] = v1;
        }
    }
#undef AS
#undef BS
}

// ---------------- grid barrier ---------------------------------------------------
__device__ __forceinline__ void grid_sync() {
    __syncthreads();
    if (threadIdx.x == 0) {
        __threadfence();
        ull t = atomicAdd(&g_bar, 1ull) + 1ull;
        ull target = ((t - 1ull) / NBLK + 1ull) * (ull)NBLK;
        volatile ull* vb = &g_bar;
        while (*vb < target) { }
        __threadfence();
    }
    __syncthreads();
}

// ---------------- persistent recurrence ------------------------------------------
// 128 CTAs x 512 threads. CTA owns 4 hidden columns (3 gates each).
// warp = 32-k slice (16 warps), 2 pipelined 16-k chunks.
// lane: btile = lane>>1 (4 batches), ct = lane&1 (col pair).
#define WSM_PITCH 16
#define SMEM_FLOATS (HH * BB + HH * WSM_PITCH + 32 * 192 * 2)

__global__ __launch_bounds__(RTH) void gru_recurrence(
    const float* __restrict__ whr, const float* __restrict__ whz,
    const float* __restrict__ whn,
    const float* __restrict__ bhr, const float* __restrict__ bhz,
    const float* __restrict__ bhn,
    float* __restrict__ seq,          // [T,B,H]
    float* __restrict__ finals)       // [B,H]
{
    extern __shared__ float sm[];
    float* ht  = sm;                          // [512][64] h (k-major)
    float* wsm = sm + HH * BB;                // [512][16] (12 used: g*4+j)
    ull*   red = (ull*)(sm + HH * BB + HH * WSM_PITCH);  // [32][192]

    const int tid = threadIdx.x;
    const int w   = tid >> 5;                 // warp = 32-k slice (0..15)
    const int lane = tid & 31;
    const int btile = lane >> 1;              // 0..15 -> 4 batches
    const int ct = lane & 1;                  // col pair 2*ct, 2*ct+1
    const int jbase = blockIdx.x * 4;

    // activation-phase identity (threads 0..255 only)
    const int ab = (tid >> 2) & 63;
    const int aj = tid & 3;
    const int jglob = jbase + aj;
    const int act = aj >> 1;
    const int ahalf = aj & 1;

    // load weight columns (once): wsm[k][g*4+j] = W_g[k][jbase+j]
    for (int i = tid; i < HH * 12; i += RTH) {
        const int k = i / 12;
        const int rr = i - k * 12;
        const int g = rr >> 2;
        const int j = rr & 3;
        const float* src = (g == 0) ? whr : ((g == 1) ? whz : whn);
        wsm[k * WSM_PITCH + rr] = src[(size_t)k * HH + jbase + j];
    }
    const float bh_r = bhr[jglob];
    const float bh_z = bhz[jglob];
    const float bh_n = bhn[jglob];
    __syncthreads();

    const float* hbase = ht + btile * 4;
    const float* wbase = wsm + ct * 2;
    float4* ht4 = (float4*)ht;
    const int slice_f4 = w * (32 * BB / 4);   // 512 float4 per slice, 256/chunk

    for (int t = 0; t < TT; t++) {
        // prefetch gate-x (hidden under dot); only activation threads need it
        const int gi = (t * BB + ab) * HH + jglob;
        float gxr = 0.f, gxz = 0.f, gxn = 0.f;
        if (tid < 256) {
            gxr = __ldcs(&g_gx[0][gi]);
            gxz = __ldcs(&g_gx[1][gi]);
            gxn = __ldcs(&g_gx[2][gi]);
        }

        const float4* src4 = (const float4*)g_ht[(t - 1) & 1];

        ull a0r = 0, a1r = 0, a2r = 0, a3r = 0;
        ull a0z = 0, a1z = 0, a2z = 0, a3z = 0;
        ull a0n = 0, a1n = 0, a2n = 0, a3n = 0;

        float4 pf[8];
        // chunk 0: load + store
#pragma unroll
        for (int i = 0; i < 8; i++)
            pf[i] = __ldcg(&src4[slice_f4 + i * 32 + lane]);
#pragma unroll
        for (int i = 0; i < 8; i++)
            ht4[slice_f4 + i * 32 + lane] = pf[i];
        // chunk 1 loads in flight under chunk-0 compute
#pragma unroll
        for (int i = 0; i < 8; i++)
            pf[i] = __ldcg(&src4[slice_f4 + 256 + i * 32 + lane]);
        __syncwarp();

#pragma unroll
        for (int kk = 0; kk < 16; kk++) {
            const int k = (w << 5) + kk;
            float4 h4 = *(const float4*)(hbase + k * BB);
            ull wr = *(const ull*)(wbase + k * WSM_PITCH + 0);
            ull wz = *(const ull*)(wbase + k * WSM_PITCH + 4);
            ull wn = *(const ull*)(wbase + k * WSM_PITCH + 8);
            ull h0p = pk2(h4.x), h1p = pk2(h4.y), h2p = pk2(h4.z), h3p = pk2(h4.w);
            fma2(a0r, h0p, wr); fma2(a1r, h1p, wr); fma2(a2r, h2p, wr); fma2(a3r, h3p, wr);
            fma2(a0z, h0p, wz); fma2(a1z, h1p, wz); fma2(a2z, h2p, wz); fma2(a3z, h3p, wz);
            fma2(a0n, h0p, wn); fma2(a1n, h1p, wn); fma2(a2n, h2p, wn); fma2(a3n, h3p, wn);
        }

#pragma unroll
        for (int i = 0; i < 8; i++)
            ht4[slice_f4 + 256 + i * 32 + lane] = pf[i];
        __syncwarp();

#pragma unroll
        for (int kk = 16; kk < 32; kk++) {
            const int k = (w << 5) + kk;
            float4 h4 = *(const float4*)(hbase + k * BB);
            ull wr = *(const ull*)(wbase + k * WSM_PITCH + 0);
            ull wz = *(const ull*)(wbase + k * WSM_PITCH + 4);
            ull wn = *(const ull*)(wbase + k * WSM_PITCH + 8);
            ull h0p = pk2(h4.x), h1p = pk2(h4.y), h2p = pk2(h4.z), h3p = pk2(h4.w);
            fma2(a0r, h0p, wr); fma2(a1r, h1p, wr); fma2(a2r, h2p, wr); fma2(a3r, h3p, wr);
            fma2(a0z, h0p, wz); fma2(a1z, h1p, wz); fma2(a2z, h2p, wz); fma2(a3z, h3p, wz);
            fma2(a0n, h0p, wn); fma2(a1n, h1p, wn); fma2(a2n, h2p, wn); fma2(a3n, h3p, wn);
        }

        // store partials: red[w*2+ct][g*64 + b]
        {
            ull* rb = red + (size_t)(w * 2 + ct) * 192;
            const int b0 = btile * 4;
            rb[0 * 64 + b0 + 0] = a0r; rb[0 * 64 + b0 + 1] = a1r;
            rb[0 * 64 + b0 + 2] = a2r; rb[0 * 64 + b0 + 3] = a3r;
            rb[1 * 64 + b0 + 0] = a0z; rb[1 * 64 + b0 + 1] = a1z;
            rb[1 * 64 + b0 + 2] = a2z; rb[1 * 64 + b0 + 3] = a3z;
            rb[2 * 64 + b0 + 0] = a0n; rb[2 * 64 + b0 + 1] = a1n;
            rb[2 * 64 + b0 + 2] = a2n; rb[2 * 64 + b0 + 3] = a3n;
        }
        __syncthreads();

        // ---- reduce over 16 slices + activation (threads 0..255) ----
        if (tid < 256) {
            float ar = bh_r, az = bh_z, an = bh_n;
            const float* rf = (const float*)red;
#pragma unroll
            for (int ww = 0; ww < 16; ww++) {
                const size_t base = ((size_t)(ww * 2 + act) * 192) * 2 + ahalf;
                ar += rf[base + (0 * 64 + ab) * 2];
                az += rf[base + (1 * 64 + ab) * 2];
                an += rf[base + (2 * 64 + ab) * 2];
            }

            const float rg = 1.f / (1.f + expf(-(gxr + ar)));
            const float zg = 1.f / (1.f + expf(-(gxz + az)));
            const float ng = tanhf(gxn + rg * an);
            const float hp = ht[jglob * BB + ab];
            const float hn_ = (1.f - zg) * ng + zg * hp;

            __stcg(&g_ht[t & 1][jglob * BB + ab], hn_);   // k-major for next step
            seq[gi] = hn_;
            if (t == TT - 1) finals[(size_t)ab * HH + jglob] = hn_;
        }

        grid_sync();
    }
}

// -------------------------------- launch -----------------------------------------
extern "C" void kernel_launch(void* const* d_in, const int* in_sizes, int n_in,
                              void* d_out, int out_size) {
    const float* x    = (const float*)d_in[0];
    const float* init = (const float*)d_in[1];
    const float* w_ir = (const float*)d_in[2];
    const float* w_hr = (const float*)d_in[3];
    const float* w_iz = (const float*)d_in[4];
    const float* w_hz = (const float*)d_in[5];
    const float* w_in = (const float*)d_in[6];
    const float* w_hn = (const float*)d_in[7];
    const float* b_ir = (const float*)d_in[8];
    const float* b_hr = (const float*)d_in[9];
    const float* b_iz = (const float*)d_in[10];
    const float* b_hz = (const float*)d_in[11];
    const float* b_in = (const float*)d_in[12];
    const float* b_hn = (const float*)d_in[13];

    float* out    = (float*)d_out;
    float* seq    = out;                          // [T,B,H]
    float* finals = out + (size_t)TT * BB * HH;   // [L,B,H]

    const size_t rec_smem = (size_t)SMEM_FLOATS * sizeof(float);
    cudaFuncSetAttribute(gru_recurrence,
                         cudaFuncAttributeMaxDynamicSharedMemorySize,
                         (int)rec_smem);
    const size_t gemm_smem = (size_t)GEMM_SMEM_FLOATS * sizeof(float);
    cudaFuncSetAttribute(gemm_xw_mma,
                         cudaFuncAttributeMaxDynamicSharedMemorySize,
                         (int)gemm_smem);

    dim3 ggrid(TT * BB / 128, HH / 128, 3);       // 256 x 4 x 3

    for (int l = 0; l < LL; l++) {
        const float* A = (l == 0) ? x : seq;
        const size_t wo = (size_t)l * HH * HH;
        const size_t bo = (size_t)l * HH;

        gemm_xw_mma<<<ggrid, 256, gemm_smem>>>(A,
                                               w_ir + wo, w_iz + wo, w_in + wo,
                                               b_ir + bo, b_iz + bo, b_in + bo);

        transpose_h0<<<HH * BB / 256, 256>>>(init + (size_t)l * BB * HH);

        gru_recurrence<<<NBLK, RTH, rec_smem>>>(
            w_hr + wo, w_hz + wo, w_hn + wo,
            b_hr + bo, b_hz + bo, b_hn + bo,
            seq,
            finals + (size_t)l * BB * HH);
    }
}